// round 6
// baseline (speedup 1.0000x reference)
#include <cuda_runtime.h>
#include <cstdint>

#define NN    4096
#define FIN   128
#define NH    8
#define FO    64
#define FTOT  512
#define KT    64
#define NSPL  2
#define JSPL  (NN / NSPL)          // 2048 j per split
#define NKT   (JSPL / KT)          // 32 tiles per split
#define LOG2E 1.4426950408889634f

#define VSTRIDE 72                 // floats per SMEM V row (64 data + 8 pad)
#define STG_V   (KT * VSTRIDE * 4) // 18432 B per stage
#define STG_T   512                // 32 float4 per stage
#define SMEM_DYN (3 * STG_V + 3 * STG_T)

// ---------------- scratch (static device memory only) ----------------
__device__ float g_ht[NN * FTOT];              // 8 MB: hW flat == ht[h][n][o]
__device__ float g_src[NH * NN];
__device__ float g_tgt[NH * NN];
__device__ unsigned g_Tbits[NH];               // per-head max(tgt), monotonic enc
__device__ unsigned g_adjb[NN * NN / 32];      // 2 MB bit-packed adjacency
__device__ float4 g_tp[NH * (NN / 8) * 4];     // 256 KB pair table
__device__ float g_part[NSPL][NH * NN * FO];   // 16 MB split numerators
__device__ float g_psum[NSPL][NH * NN];        // split denominators

// ---------------- helpers ----------------
__device__ __forceinline__ unsigned encf(float f) {
    unsigned b = __float_as_uint(f);
    return (b & 0x80000000u) ? ~b : (b | 0x80000000u);
}
__device__ __forceinline__ float decf(unsigned k) {
    unsigned b = (k & 0x80000000u) ? (k & 0x7FFFFFFFu) : ~k;
    return __uint_as_float(b);
}
__device__ __forceinline__ float ex2f(float x) {
    float r;
    asm("ex2.approx.f32 %0, %1;" : "=f"(r) : "f"(x));
    return r;
}
__device__ __forceinline__ unsigned long long pack2(float x, float y) {
    unsigned long long r;
    asm("mov.b64 %0, {%1, %2};" : "=l"(r) : "f"(x), "f"(y));
    return r;
}
__device__ __forceinline__ void unpack2(unsigned long long v, float& x, float& y) {
    asm("mov.b64 {%0, %1}, %2;" : "=f"(x), "=f"(y) : "l"(v));
}
__device__ __forceinline__ unsigned long long add2(unsigned long long a,
                                                   unsigned long long b) {
    unsigned long long d;
    asm("add.rn.f32x2 %0, %1, %2;" : "=l"(d) : "l"(a), "l"(b));
    return d;
}
__device__ __forceinline__ unsigned long long ffma2(unsigned long long a,
                                                    unsigned long long b,
                                                    unsigned long long c) {
    unsigned long long d;
    asm("fma.rn.f32x2 %0, %1, %2, %3;" : "=l"(d) : "l"(a), "l"(b), "l"(c));
    return d;
}
__device__ __forceinline__ uint32_t smem_u32(const void* p) {
    uint32_t a;
    asm("{ .reg .u64 t; cvta.to.shared.u64 t, %1; cvt.u32.u64 %0, t; }"
        : "=r"(a) : "l"(p));
    return a;
}
__device__ __forceinline__ void cp16(uint32_t dst, const void* src) {
    asm volatile("cp.async.cg.shared.global [%0], [%1], 16;"
                 :: "r"(dst), "l"(src) : "memory");
}
__device__ __forceinline__ void cp_commit() {
    asm volatile("cp.async.commit_group;" ::: "memory");
}
__device__ __forceinline__ void mma_tf32(float c[4], uint32_t a0, uint32_t a1,
                                         uint32_t a2, uint32_t a3,
                                         uint32_t b0, uint32_t b1) {
    asm volatile(
        "mma.sync.aligned.m16n8k8.row.col.f32.tf32.tf32.f32 "
        "{%0,%1,%2,%3}, {%4,%5,%6,%7}, {%8,%9}, {%0,%1,%2,%3};"
        : "+f"(c[0]), "+f"(c[1]), "+f"(c[2]), "+f"(c[3])
        : "r"(a0), "r"(a1), "r"(a2), "r"(a3), "r"(b0), "r"(b1));
}

// ---------------- kernel A: hW = h @ W + fused adjacency pack ----------------
// GEMM is FMA/LDS bound, adjacency pack is DRAM bound: fused they overlap.
__global__ void __launch_bounds__(256)
k_gemmpack(const float* __restrict__ H, const float* __restrict__ W,
           const int* __restrict__ adj) {
    __shared__ float sA[64][68];
    __shared__ float sW[64][64];
    const int row0 = blockIdx.x * 64, col0 = blockIdx.y * 64, t = threadIdx.x;
    const int r = t >> 3, c0 = (t & 7) * 8;

    if (blockIdx.x == 0 && blockIdx.y == 0 && t < NH) g_Tbits[t] = 0u;

    unsigned long long accP[2][4];
#pragma unroll
    for (int i = 0; i < 2; ++i)
#pragma unroll
        for (int p = 0; p < 4; ++p) accP[i][p] = 0ull;

    for (int kk = 0; kk < FIN; kk += 64) {
#pragma unroll
        for (int u = 0; u < 4; ++u) {
            int idx = t + u * 256;
            int rr = idx >> 4, q = idx & 15;
            float4 v = *(const float4*)(H + (size_t)(row0 + rr) * FIN + kk + q * 4);
            *(float4*)&sA[rr][q * 4] = v;
        }
#pragma unroll
        for (int u = 0; u < 4; ++u) {
            int idx = t + u * 256;
            int k = idx >> 4, q = idx & 15;
            float4 v = *(const float4*)(W + (size_t)(kk + k) * FTOT + col0 + q * 4);
            *(float4*)&sW[k][q * 4] = v;
        }
        __syncthreads();
#pragma unroll
        for (int k = 0; k < 64; ++k) {
            unsigned long long a0P = pack2(sA[r][k], sA[r][k]);
            unsigned long long a1P = pack2(sA[r + 32][k], sA[r + 32][k]);
            const unsigned long long* wP = (const unsigned long long*)&sW[k][c0];
#pragma unroll
            for (int p = 0; p < 4; ++p) {
                accP[0][p] = ffma2(a0P, wP[p], accP[0][p]);
                accP[1][p] = ffma2(a1P, wP[p], accP[1][p]);
            }
        }
        __syncthreads();
    }
#pragma unroll
    for (int i = 0; i < 2; ++i) {
        float* o = g_ht + (size_t)(row0 + r + i * 32) * FTOT + col0 + c0;
#pragma unroll
        for (int p = 0; p < 4; ++p) {
            float x, y;
            unpack2(accP[i][p], x, y);
            o[2 * p] = x; o[2 * p + 1] = y;
        }
    }

    // ---- fused adjacency bit-pack (independent of GEMM result) ----
    const int lane = t & 31;
    const int bflat = blockIdx.y * gridDim.x + blockIdx.x;   // 0..511
    const int gw0 = bflat * 8 + (t >> 5);                    // 0..4095
    const int NW = NN * NN / 32;
    for (int w = gw0; w < NW; w += 4096) {
        int v = adj[(size_t)w * 32 + lane];
        unsigned m = __ballot_sync(0xFFFFFFFFu, v != 0);
        if (lane == 0) g_adjb[w] = m;
    }
}

// ---------------- src/tgt projections + fused per-head max ----------------
__global__ void k_srctgt(const float* __restrict__ a) {
    const int warp = threadIdx.x >> 5, lane = threadIdx.x & 31;
    const int gw = blockIdx.x * 8 + warp;
    const int h = gw >> 12;
    const int n = gw & (NN - 1);
    const float* htp = g_ht + (size_t)h * (NN * FO) + (size_t)n * FO;
    float v0 = htp[lane], v1 = htp[lane + 32];
    float a0 = a[h * 128 + lane],      a1 = a[h * 128 + lane + 32];
    float b0 = a[h * 128 + 64 + lane], b1 = a[h * 128 + 96 + lane];
    float s  = v0 * a0 + v1 * a1;
    float tg = v0 * b0 + v1 * b1;
#pragma unroll
    for (int off = 16; off; off >>= 1) {
        s  += __shfl_down_sync(0xFFFFFFFFu, s, off);
        tg += __shfl_down_sync(0xFFFFFFFFu, tg, off);
    }
    if (lane == 0) {
        g_src[h * NN + n] = s;
        g_tgt[h * NN + n] = tg;
        atomicMax(&g_Tbits[h], encf(tg));
    }
}

// ---------------- prep: pairwise (tgt*L, 0.2*L*tgt) table ----------------
__global__ void k_prep() {
    const int idx = blockIdx.x * 256 + threadIdx.x;     // 16384
    const int h = idx >> 11;
    const int bq = idx & 2047;
    const int b = bq >> 2, q = bq & 3;
    const float* tp = g_tgt + h * NN + b * 8;
    float t1 = tp[q], t2 = tp[q + 4];
    g_tp[idx] = make_float4(t1 * LOG2E, t2 * LOG2E,
                            t1 * (0.2f * LOG2E), t2 * (0.2f * LOG2E));
}

// ---------------- kernel C: fused masked-softmax @ V ----------------
// block = (head, 128-row i-tile, k-split); 4 warps, m32 rows each.
// 3-stage cp.async pipeline, one __syncthreads per tile, adj prefetch.
// Denominator via ones-column (nb=8); HMMA truncation replaces tf32 cvt.
__global__ void __launch_bounds__(128, 4)
k_attn_mma(const unsigned* __restrict__ adjb, float* __restrict__ part,
           float* __restrict__ psums) {
    extern __shared__ float dynf[];

    const int head  = blockIdx.x;
    const int ibase = blockIdx.y * 128;
    const int spl   = blockIdx.z;
    const int jbase = spl * JSPL;
    const int t     = threadIdx.x;
    const int wid   = t >> 5;
    const int lane  = t & 31;
    const int g     = lane >> 2;
    const int tg4   = lane & 3;

    const int rbase = ibase + wid * 32 + g;       // rows rbase + {0,8,16,24}

    const float Th = decf(g_Tbits[head]);
    unsigned long long srcP[4], src02P[4];
#pragma unroll
    for (int rg = 0; rg < 4; ++rg) {
        float src = g_src[head * NN + rbase + rg * 8];
        float e0 = src + Th;
        float mm = fmaxf(e0, 0.2f * e0) * LOG2E;  // >= scaled row max
        srcP[rg]   = pack2(src * LOG2E - mm, src * LOG2E - mm);
        src02P[rg] = pack2(src * (0.2f * LOG2E) - mm, src * (0.2f * LOG2E) - mm);
    }

    const unsigned* abase = adjb + (size_t)rbase * (NN / 32) + (jbase / 32);
    const float* vp = g_ht + (size_t)head * (NN * FO) + (size_t)jbase * FO;
    const float4* tpp = g_tp + (size_t)head * (NN / 8) * 4 + (size_t)(jbase / 8) * 4;

    const uint32_t svb = smem_u32(dynf);
    const uint32_t stb = svb + 3 * STG_V;
    const float4* stp = (const float4*)(dynf + 3 * (STG_V / 4));

    // pad columns 64..71 of all 3 stages: col64 = 1 (denominator), rest 0
    for (int idx = t; idx < 3 * KT * 8; idx += 128) {
        int st = idx / (KT * 8), rem = idx % (KT * 8);
        int r = rem >> 3, cc = rem & 7;
        dynf[st * (STG_V / 4) + r * VSTRIDE + 64 + cc] = (cc == 0) ? 1.0f : 0.0f;
    }

    float acc[2][9][4];
#pragma unroll
    for (int gr = 0; gr < 2; ++gr)
#pragma unroll
        for (int nb = 0; nb < 9; ++nb)
#pragma unroll
            for (int q = 0; q < 4; ++q) acc[gr][nb][q] = 0.f;

    auto load_tile = [&](int kt, int st) {
        const float* base = vp + (size_t)kt * KT * FO;
        const uint32_t sb = svb + (uint32_t)st * STG_V;
#pragma unroll
        for (int u = 0; u < 8; ++u) {
            int idx = t + u * 128;            // 1024 16B chunks
            int r = idx >> 4, q = idx & 15;
            cp16(sb + (uint32_t)r * (VSTRIDE * 4) + (uint32_t)q * 16,
                 base + (size_t)r * FO + q * 4);
        }
        if (t < 32)
            cp16(stb + (uint32_t)st * STG_T + (uint32_t)t * 16, tpp + kt * 32 + t);
        cp_commit();
    };
    auto load_adj = [&](int kt, unsigned long long wb[4]) {
#pragma unroll
        for (int rg = 0; rg < 4; ++rg) {
            uint2 w2 = *(const uint2*)(abase + (size_t)rg * 8 * (NN / 32) + 2 * kt);
            wb[rg] = (unsigned long long)w2.x | ((unsigned long long)w2.y << 32);
        }
    };

    load_tile(0, 0);
    load_tile(1, 1);
    unsigned long long wbcur[4], wbnext[4];
    load_adj(0, wbcur);

    for (int kt = 0; kt < NKT; ++kt) {
        const int st = kt % 3;
        if (kt + 2 < NKT) {
            asm volatile("cp.async.wait_group 1;" ::: "memory");
        } else {
            asm volatile("cp.async.wait_group 0;" ::: "memory");
        }
        __syncthreads();                       // single barrier per tile
        if (kt + 2 < NKT) load_tile(kt + 2, (kt + 2) % 3);
        if (kt + 1 < NKT) load_adj(kt + 1, wbnext);

        const float* sVs = dynf + st * (STG_V / 4);
        const float4* stq = stp + st * 32;

#pragma unroll
        for (int ks = 0; ks < 8; ++ks) {
            const float4 tq = stq[ks * 4 + tg4];
            const unsigned long long tLP  = pack2(tq.x, tq.y);
            const unsigned long long t02P = pack2(tq.z, tq.w);
            const int c1 = ks * 8 + tg4;

            uint32_t aw[4][2];
#pragma unroll
            for (int rg = 0; rg < 4; ++rg) {
                unsigned long long t1 = add2(srcP[rg], tLP);
                unsigned long long t2 = add2(src02P[rg], t02P);
                float x1, y1, x2, y2;
                unpack2(t1, x1, y1);
                unpack2(t2, x2, y2);
                float w1 = ex2f(fmaxf(x1, x2));
                float w2 = ex2f(fmaxf(y1, y2));
                unsigned bs = (unsigned)(wbcur[rg] >> c1);
                w1 = (bs & 1u)  ? w1 : 0.0f;
                w2 = (bs & 16u) ? w2 : 0.0f;
                aw[rg][0] = __float_as_uint(w1);
                aw[rg][1] = __float_as_uint(w2);
            }
#pragma unroll
            for (int nb = 0; nb < 9; ++nb) {
                uint32_t b0 = __float_as_uint(sVs[c1 * VSTRIDE + nb * 8 + g]);
                uint32_t b1 = __float_as_uint(sVs[(c1 + 4) * VSTRIDE + nb * 8 + g]);
                mma_tf32(acc[0][nb], aw[0][0], aw[1][0], aw[0][1], aw[1][1], b0, b1);
                mma_tf32(acc[1][nb], aw[2][0], aw[3][0], aw[2][1], aw[3][1], b0, b1);
            }
        }
#pragma unroll
        for (int rg = 0; rg < 4; ++rg) wbcur[rg] = wbnext[rg];
    }

    // ---- denominator partials (ones-column, lanes with tg4==0) ----
    float* psp = psums + (size_t)spl * (NH * NN) + head * NN;
    if (tg4 == 0) {
        psp[rbase]      = acc[0][8][0];
        psp[rbase + 8]  = acc[0][8][2];
        psp[rbase + 16] = acc[1][8][0];
        psp[rbase + 24] = acc[1][8][2];
    }

    // ---- numerator partials ----
    float* pp = part + (size_t)spl * (NH * NN * FO) + ((size_t)head * NN) * FO;
#pragma unroll
    for (int gr = 0; gr < 2; ++gr) {
        float* o1 = pp + (size_t)(rbase + gr * 16) * FO + 2 * tg4;
        float* o2 = o1 + 8 * FO;
#pragma unroll
        for (int nb = 0; nb < 8; ++nb) {
            *(float2*)(o1 + nb * 8) = make_float2(acc[gr][nb][0], acc[gr][nb][1]);
            *(float2*)(o2 + nb * 8) = make_float2(acc[gr][nb][2], acc[gr][nb][3]);
        }
    }
}

// ---------------- combine splits ----------------
__global__ void k_comb(float* __restrict__ out) {
    const int idx = blockIdx.x * blockDim.x + threadIdx.x;   // f4 index
    const int row = idx >> 4;                                // (h*NN + i)
    float4 n0 = *(const float4*)(&g_part[0][(size_t)idx * 4]);
    float4 n1 = *(const float4*)(&g_part[1][(size_t)idx * 4]);
    float s = g_psum[0][row] + g_psum[1][row];
    float inv = (s > 0.f) ? 1.0f / s : 0.f;
    float4 o;
    o.x = (n0.x + n1.x) * inv;
    o.y = (n0.y + n1.y) * inv;
    o.z = (n0.z + n1.z) * inv;
    o.w = (n0.w + n1.w) * inv;
    *(float4*)(out + (size_t)idx * 4) = o;
}

// ---------------- host launcher ----------------
extern "C" void kernel_launch(void* const* d_in, const int* in_sizes, int n_in,
                              void* d_out, int out_size) {
    const float* H = nullptr; const int* adj = nullptr;
    const float* W = nullptr; const float* a = nullptr;
    for (int i = 0; i < n_in; ++i) {
        switch (in_sizes[i]) {
            case NN * FIN:    H   = (const float*)d_in[i]; break;
            case NN * NN:     adj = (const int*)d_in[i];   break;
            case FIN * FTOT:  W   = (const float*)d_in[i]; break;
            case NH * 2 * FO: a   = (const float*)d_in[i]; break;
        }
    }
    float* out = (float*)d_out;

    unsigned* adjb; cudaGetSymbolAddress((void**)&adjb, g_adjb);
    float* part;    cudaGetSymbolAddress((void**)&part, g_part);
    float* psums;   cudaGetSymbolAddress((void**)&psums, g_psum);

    cudaFuncSetAttribute(k_attn_mma, cudaFuncAttributeMaxDynamicSharedMemorySize,
                         SMEM_DYN);

    k_gemmpack<<<dim3(NN / 64, FTOT / 64), 256>>>(H, W, adj);
    k_srctgt  <<<(NN * NH) / 8, 256>>>(a);
    k_prep    <<<64, 256>>>();
    k_attn_mma<<<dim3(NH, NN / 128, NSPL), 128, SMEM_DYN>>>(adjb, part, psums);
    k_comb    <<<(NH * NN * FO / 4) / 256, 256>>>(out);
}

// round 7
// speedup vs baseline: 1.2172x; 1.2172x over previous
#include <cuda_runtime.h>
#include <cuda_fp16.h>
#include <cstdint>

#define NN    4096
#define FIN   128
#define NH    8
#define FO    64
#define FTOT  512
#define KT    64
#define NSPL  2
#define JSPL  (NN / NSPL)          // 2048 j per split
#define NKT   (JSPL / KT)          // 32 tiles per split
#define LOG2E 1.4426950408889634f

#define VROWS   72                 // 64 data n-rows + 8 (ones/zeros) rows
#define VSTR    72                 // f16 per SMEM row (64 k + 8 pad)
#define STG_V   (VROWS * VSTR * 2) // 10368 B per stage
#define STG_T   512                // 32 float4 per stage
#define SMEM_DYN (3 * STG_V + 3 * STG_T)

// ---------------- scratch (static device memory only) ----------------
__device__ float g_ht[NN * FTOT];              // 8 MB: hW flat == ht[h][n][o]
__device__ float g_src[NH * NN];
__device__ float g_tgt[NH * NN];
__device__ unsigned g_Tbits[NH];               // per-head max(tgt), monotonic enc
__device__ unsigned g_adjb[NN * NN / 32];      // 2 MB bit-packed adjacency
__device__ __half g_vh[NH * FO * NN];          // 4 MB V^T f16: [h][o][j]
__device__ float4 g_tp[NH * (NN / 2)];         // 256 KB pair table {L0,L1,T0,T1}
__device__ float g_part[NSPL][NH * NN * FO];   // 16 MB split numerators
__device__ float g_psum[NSPL][NH * NN];        // split denominators

// ---------------- helpers ----------------
__device__ __forceinline__ unsigned encf(float f) {
    unsigned b = __float_as_uint(f);
    return (b & 0x80000000u) ? ~b : (b | 0x80000000u);
}
__device__ __forceinline__ float decf(unsigned k) {
    unsigned b = (k & 0x80000000u) ? (k & 0x7FFFFFFFu) : ~k;
    return __uint_as_float(b);
}
__device__ __forceinline__ float ex2f(float x) {
    float r;
    asm("ex2.approx.f32 %0, %1;" : "=f"(r) : "f"(x));
    return r;
}
__device__ __forceinline__ unsigned long long pack2(float x, float y) {
    unsigned long long r;
    asm("mov.b64 %0, {%1, %2};" : "=l"(r) : "f"(x), "f"(y));
    return r;
}
__device__ __forceinline__ void unpack2(unsigned long long v, float& x, float& y) {
    asm("mov.b64 {%0, %1}, %2;" : "=f"(x), "=f"(y) : "l"(v));
}
__device__ __forceinline__ unsigned long long add2(unsigned long long a,
                                                   unsigned long long b) {
    unsigned long long d;
    asm("add.rn.f32x2 %0, %1, %2;" : "=l"(d) : "l"(a), "l"(b));
    return d;
}
__device__ __forceinline__ unsigned long long ffma2(unsigned long long a,
                                                    unsigned long long b,
                                                    unsigned long long c) {
    unsigned long long d;
    asm("fma.rn.f32x2 %0, %1, %2, %3;" : "=l"(d) : "l"(a), "l"(b), "l"(c));
    return d;
}
__device__ __forceinline__ uint32_t f16x2(float lo, float hi) {
    uint32_t r;
    asm("cvt.rn.f16x2.f32 %0, %1, %2;" : "=r"(r) : "f"(hi), "f"(lo));
    return r;
}
__device__ __forceinline__ uint32_t smem_u32(const void* p) {
    uint32_t a;
    asm("{ .reg .u64 t; cvta.to.shared.u64 t, %1; cvt.u32.u64 %0, t; }"
        : "=r"(a) : "l"(p));
    return a;
}
__device__ __forceinline__ void cp16(uint32_t dst, const void* src) {
    asm volatile("cp.async.cg.shared.global [%0], [%1], 16;"
                 :: "r"(dst), "l"(src) : "memory");
}
__device__ __forceinline__ void cp_commit() {
    asm volatile("cp.async.commit_group;" ::: "memory");
}
// m16n8k16 fp16 inputs, fp32 accumulate
__device__ __forceinline__ void mma_f16(float c[4], uint32_t a0, uint32_t a1,
                                        uint32_t a2, uint32_t a3,
                                        uint32_t b0, uint32_t b1) {
    asm volatile(
        "mma.sync.aligned.m16n8k16.row.col.f32.f16.f16.f32 "
        "{%0,%1,%2,%3}, {%4,%5,%6,%7}, {%8,%9}, {%0,%1,%2,%3};"
        : "+f"(c[0]), "+f"(c[1]), "+f"(c[2]), "+f"(c[3])
        : "r"(a0), "r"(a1), "r"(a2), "r"(a3), "r"(b0), "r"(b1));
}

// ---------------- kernel A: hW = h @ W + fused adjacency pack ----------------
__global__ void __launch_bounds__(256)
k_gemmpack(const float* __restrict__ H, const float* __restrict__ W,
           const int* __restrict__ adj) {
    __shared__ float sA[64][68];
    __shared__ float sW[64][64];
    const int row0 = blockIdx.x * 64, col0 = blockIdx.y * 64, t = threadIdx.x;
    const int r = t >> 3, c0 = (t & 7) * 8;

    if (blockIdx.x == 0 && blockIdx.y == 0 && t < NH) g_Tbits[t] = 0u;

    unsigned long long accP[2][4];
#pragma unroll
    for (int i = 0; i < 2; ++i)
#pragma unroll
        for (int p = 0; p < 4; ++p) accP[i][p] = 0ull;

    for (int kk = 0; kk < FIN; kk += 64) {
#pragma unroll
        for (int u = 0; u < 4; ++u) {
            int idx = t + u * 256;
            int rr = idx >> 4, q = idx & 15;
            float4 v = *(const float4*)(H + (size_t)(row0 + rr) * FIN + kk + q * 4);
            *(float4*)&sA[rr][q * 4] = v;
        }
#pragma unroll
        for (int u = 0; u < 4; ++u) {
            int idx = t + u * 256;
            int k = idx >> 4, q = idx & 15;
            float4 v = *(const float4*)(W + (size_t)(kk + k) * FTOT + col0 + q * 4);
            *(float4*)&sW[k][q * 4] = v;
        }
        __syncthreads();
#pragma unroll
        for (int k = 0; k < 64; ++k) {
            unsigned long long a0P = pack2(sA[r][k], sA[r][k]);
            unsigned long long a1P = pack2(sA[r + 32][k], sA[r + 32][k]);
            const unsigned long long* wP = (const unsigned long long*)&sW[k][c0];
#pragma unroll
            for (int p = 0; p < 4; ++p) {
                accP[0][p] = ffma2(a0P, wP[p], accP[0][p]);
                accP[1][p] = ffma2(a1P, wP[p], accP[1][p]);
            }
        }
        __syncthreads();
    }
#pragma unroll
    for (int i = 0; i < 2; ++i) {
        float* o = g_ht + (size_t)(row0 + r + i * 32) * FTOT + col0 + c0;
#pragma unroll
        for (int p = 0; p < 4; ++p) {
            float x, y;
            unpack2(accP[i][p], x, y);
            o[2 * p] = x; o[2 * p + 1] = y;
        }
    }

    // ---- fused adjacency bit-pack (DRAM-bound, overlaps GEMM) ----
    const int lane = t & 31;
    const int bflat = blockIdx.y * gridDim.x + blockIdx.x;   // 0..511
    const int gw0 = bflat * 8 + (t >> 5);
    const int NW = NN * NN / 32;
    for (int w = gw0; w < NW; w += 4096) {
        int v = adj[(size_t)w * 32 + lane];
        unsigned m = __ballot_sync(0xFFFFFFFFu, v != 0);
        if (lane == 0) g_adjb[w] = m;
    }
}

// ---------------- src/tgt projections + fused per-head max ----------------
__global__ void k_srctgt(const float* __restrict__ a) {
    const int warp = threadIdx.x >> 5, lane = threadIdx.x & 31;
    const int gw = blockIdx.x * 8 + warp;
    const int h = gw >> 12;
    const int n = gw & (NN - 1);
    const float* htp = g_ht + (size_t)h * (NN * FO) + (size_t)n * FO;
    float v0 = htp[lane], v1 = htp[lane + 32];
    float a0 = a[h * 128 + lane],      a1 = a[h * 128 + lane + 32];
    float b0 = a[h * 128 + 64 + lane], b1 = a[h * 128 + 96 + lane];
    float s  = v0 * a0 + v1 * a1;
    float tg = v0 * b0 + v1 * b1;
#pragma unroll
    for (int off = 16; off; off >>= 1) {
        s  += __shfl_down_sync(0xFFFFFFFFu, s, off);
        tg += __shfl_down_sync(0xFFFFFFFFu, tg, off);
    }
    if (lane == 0) {
        g_src[h * NN + n] = s;
        g_tgt[h * NN + n] = tg;
        atomicMax(&g_Tbits[h], encf(tg));
    }
}

// ---------------- V^T f16 transpose + pair table ----------------
__global__ void __launch_bounds__(256)
k_vth() {
    __shared__ float sT[64][68];
    const int h  = blockIdx.z;
    const int j0 = blockIdx.x * 64;
    const int t  = threadIdx.x;
    const float* in = g_ht + (size_t)h * (NN * FO);

#pragma unroll
    for (int u = 0; u < 4; ++u) {
        int idx = t + u * 256;
        int r = idx >> 4, q = idx & 15;
        float4 v = *(const float4*)(in + (size_t)(j0 + r) * FO + q * 4);
        *(float4*)&sT[r][q * 4] = v;
    }
    __syncthreads();

    const int o = t >> 2, jq = (t & 3) * 16;
    uint32_t buf[8];
#pragma unroll
    for (int jj = 0; jj < 8; ++jj)
        buf[jj] = f16x2(sT[jq + 2 * jj][o], sT[jq + 2 * jj + 1][o]);
    uint32_t* op = (uint32_t*)(g_vh + ((size_t)h * FO + o) * NN + j0 + jq);
    *(uint4*)(op)     = make_uint4(buf[0], buf[1], buf[2], buf[3]);
    *(uint4*)(op + 4) = make_uint4(buf[4], buf[5], buf[6], buf[7]);

    if (t < 32) {
        float t1 = g_tgt[h * NN + j0 + 2 * t];
        float t2 = g_tgt[h * NN + j0 + 2 * t + 1];
        g_tp[h * (NN / 2) + j0 / 2 + t] =
            make_float4(t1 * LOG2E, t2 * LOG2E,
                        t1 * (0.2f * LOG2E), t2 * (0.2f * LOG2E));
    }
}

// ---------------- kernel C: fused masked-softmax @ V (fp16 m16n8k16) ----------------
// block = (head, 128-row i-tile, k-split); 4 warps, m32 rows each.
// B = V^T f16 [n][k] SMEM tile, 3-stage cp.async. Ones-row n=64 => denominator.
__global__ void __launch_bounds__(128, 4)
k_attn_mma(const unsigned* __restrict__ adjb, float* __restrict__ part,
           float* __restrict__ psums) {
    extern __shared__ float dynf[];
    __half* svh = (__half*)dynf;

    const int head  = blockIdx.x;
    const int ibase = blockIdx.y * 128;
    const int spl   = blockIdx.z;
    const int jbase = spl * JSPL;
    const int t     = threadIdx.x;
    const int wid   = t >> 5;
    const int lane  = t & 31;
    const int g     = lane >> 2;
    const int tg4   = lane & 3;

    const int rbase = ibase + wid * 32 + g;       // rows rbase + {0,8,16,24}

    const float Th = decf(g_Tbits[head]);
    unsigned long long srcP[4], src02P[4];
#pragma unroll
    for (int rg = 0; rg < 4; ++rg) {
        float src = g_src[head * NN + rbase + rg * 8];
        float e0 = src + Th;
        float mm = fmaxf(e0, 0.2f * e0) * LOG2E;  // >= scaled row max
        srcP[rg]   = pack2(src * LOG2E - mm, src * LOG2E - mm);
        src02P[rg] = pack2(src * (0.2f * LOG2E) - mm, src * (0.2f * LOG2E) - mm);
    }

    const unsigned* abase = adjb + (size_t)rbase * (NN / 32) + (jbase / 32);
    const __half* vhp = g_vh + (size_t)head * FO * NN + jbase;   // [o][j]
    const float4* tpp = g_tp + (size_t)head * (NN / 2) + jbase / 2;

    const uint32_t svb = smem_u32(dynf);
    const uint32_t stb = svb + 3 * STG_V;
    const float4* stp = (const float4*)((const char*)dynf + 3 * STG_V);

    // rows 64..71 of every stage: row 64 = 1.0 (denominator), 65..71 = 0
    for (int idx = t; idx < 3 * 8 * VSTR; idx += 128) {
        int st = idx / (8 * VSTR), rem = idx % (8 * VSTR);
        int rr = rem / VSTR, kk = rem % VSTR;
        svh[st * (STG_V / 2) + (64 + rr) * VSTR + kk] =
            (rr == 0) ? __float2half(1.0f) : __float2half(0.0f);
    }

    float acc[2][9][4];
#pragma unroll
    for (int gr = 0; gr < 2; ++gr)
#pragma unroll
        for (int nb = 0; nb < 9; ++nb)
#pragma unroll
            for (int q = 0; q < 4; ++q) acc[gr][nb][q] = 0.f;

    auto load_tile = [&](int kt, int st) {
        const __half* base = vhp + (size_t)kt * KT;
        const uint32_t sb = svb + (uint32_t)st * STG_V;
#pragma unroll
        for (int u = 0; u < 4; ++u) {
            int idx = t + u * 128;            // 512 16B chunks (64 rows x 8)
            int r = idx >> 3, q = idx & 7;
            cp16(sb + (uint32_t)r * (VSTR * 2) + (uint32_t)q * 16,
                 base + (size_t)r * NN + q * 8);
        }
        if (t < 32)
            cp16(stb + (uint32_t)st * STG_T + (uint32_t)t * 16, tpp + kt * 32 + t);
        cp_commit();
    };
    auto load_adj = [&](int kt, unsigned long long wb[4]) {
#pragma unroll
        for (int rg = 0; rg < 4; ++rg) {
            uint2 w2 = *(const uint2*)(abase + (size_t)rg * 8 * (NN / 32) + 2 * kt);
            wb[rg] = (unsigned long long)w2.x | ((unsigned long long)w2.y << 32);
        }
    };

    load_tile(0, 0);
    load_tile(1, 1);
    unsigned long long wbcur[4], wbnext[4];
    load_adj(0, wbcur);

    for (int kt = 0; kt < NKT; ++kt) {
        const int st = kt % 3;
        if (kt + 2 < NKT) {
            asm volatile("cp.async.wait_group 1;" ::: "memory");
        } else {
            asm volatile("cp.async.wait_group 0;" ::: "memory");
        }
        __syncthreads();
        if (kt + 2 < NKT) load_tile(kt + 2, (kt + 2) % 3);
        if (kt + 1 < NKT) load_adj(kt + 1, wbnext);

        const __half* sVs = svh + st * (STG_V / 2);
        const float4* stq = stp + st * 32;

#pragma unroll
        for (int ks = 0; ks < 4; ++ks) {
            const float4 q1 = stq[ks * 8 + tg4];        // cols 2tg4, 2tg4+1
            const float4 q2 = stq[ks * 8 + 4 + tg4];    // cols 2tg4+8, +9
            const unsigned long long tAL = pack2(q1.x, q1.y);
            const unsigned long long tA2 = pack2(q1.z, q1.w);
            const unsigned long long tBL = pack2(q2.x, q2.y);
            const unsigned long long tB2 = pack2(q2.z, q2.w);
            const int shft = ks * 16 + 2 * tg4;

            uint32_t alo[4], ahi[4];
#pragma unroll
            for (int rg = 0; rg < 4; ++rg) {
                const unsigned bs = (unsigned)(wbcur[rg] >> shft);
                float x1, y1, x2, y2;
                unpack2(add2(srcP[rg], tAL), x1, y1);
                unpack2(add2(src02P[rg], tA2), x2, y2);
                float w0 = ex2f(fmaxf(x1, x2)); w0 = (bs & 1u)   ? w0 : 0.f;
                float w1 = ex2f(fmaxf(y1, y2)); w1 = (bs & 2u)   ? w1 : 0.f;
                alo[rg] = f16x2(w0, w1);
                unpack2(add2(srcP[rg], tBL), x1, y1);
                unpack2(add2(src02P[rg], tB2), x2, y2);
                float w2 = ex2f(fmaxf(x1, x2)); w2 = (bs & 256u) ? w2 : 0.f;
                float w3 = ex2f(fmaxf(y1, y2)); w3 = (bs & 512u) ? w3 : 0.f;
                ahi[rg] = f16x2(w2, w3);
            }
            const int kb = ks * 16 + 2 * tg4;
#pragma unroll
            for (int nb = 0; nb < 9; ++nb) {
                const __half* brow = sVs + (nb * 8 + g) * VSTR + kb;
                uint32_t b0 = *(const uint32_t*)(brow);
                uint32_t b1 = *(const uint32_t*)(brow + 8);
                mma_f16(acc[0][nb], alo[0], alo[1], ahi[0], ahi[1], b0, b1);
                mma_f16(acc[1][nb], alo[2], alo[3], ahi[2], ahi[3], b0, b1);
            }
        }
#pragma unroll
        for (int rg = 0; rg < 4; ++rg) wbcur[rg] = wbnext[rg];
    }

    // ---- denominator partials (ones-row n=64 -> tg4==0, c0/c2) ----
    float* psp = psums + (size_t)spl * (NH * NN) + head * NN;
    if (tg4 == 0) {
        psp[rbase]      = acc[0][8][0];
        psp[rbase + 8]  = acc[0][8][2];
        psp[rbase + 16] = acc[1][8][0];
        psp[rbase + 24] = acc[1][8][2];
    }

    // ---- numerator partials ----
    float* pp = part + (size_t)spl * (NH * NN * FO) + ((size_t)head * NN) * FO;
#pragma unroll
    for (int gr = 0; gr < 2; ++gr) {
        float* o1 = pp + (size_t)(rbase + gr * 16) * FO + 2 * tg4;
        float* o2 = o1 + 8 * FO;
#pragma unroll
        for (int nb = 0; nb < 8; ++nb) {
            *(float2*)(o1 + nb * 8) = make_float2(acc[gr][nb][0], acc[gr][nb][1]);
            *(float2*)(o2 + nb * 8) = make_float2(acc[gr][nb][2], acc[gr][nb][3]);
        }
    }
}

// ---------------- combine splits ----------------
__global__ void k_comb(float* __restrict__ out) {
    const int idx = blockIdx.x * blockDim.x + threadIdx.x;   // f4 index
    const int row = idx >> 4;                                // (h*NN + i)
    float4 n0 = *(const float4*)(&g_part[0][(size_t)idx * 4]);
    float4 n1 = *(const float4*)(&g_part[1][(size_t)idx * 4]);
    float s = g_psum[0][row] + g_psum[1][row];
    float inv = (s > 0.f) ? 1.0f / s : 0.f;
    float4 o;
    o.x = (n0.x + n1.x) * inv;
    o.y = (n0.y + n1.y) * inv;
    o.z = (n0.z + n1.z) * inv;
    o.w = (n0.w + n1.w) * inv;
    *(float4*)(out + (size_t)idx * 4) = o;
}

// ---------------- host launcher ----------------
extern "C" void kernel_launch(void* const* d_in, const int* in_sizes, int n_in,
                              void* d_out, int out_size) {
    const float* H = nullptr; const int* adj = nullptr;
    const float* W = nullptr; const float* a = nullptr;
    for (int i = 0; i < n_in; ++i) {
        switch (in_sizes[i]) {
            case NN * FIN:    H   = (const float*)d_in[i]; break;
            case NN * NN:     adj = (const int*)d_in[i];   break;
            case FIN * FTOT:  W   = (const float*)d_in[i]; break;
            case NH * 2 * FO: a   = (const float*)d_in[i]; break;
        }
    }
    float* out = (float*)d_out;

    unsigned* adjb; cudaGetSymbolAddress((void**)&adjb, g_adjb);
    float* part;    cudaGetSymbolAddress((void**)&part, g_part);
    float* psums;   cudaGetSymbolAddress((void**)&psums, g_psum);

    cudaFuncSetAttribute(k_attn_mma, cudaFuncAttributeMaxDynamicSharedMemorySize,
                         SMEM_DYN);

    k_gemmpack<<<dim3(NN / 64, FTOT / 64), 256>>>(H, W, adj);
    k_srctgt  <<<(NN * NH) / 8, 256>>>(a);
    k_vth     <<<dim3(NN / 64, 1, NH), 256>>>();
    k_attn_mma<<<dim3(NH, NN / 128, NSPL), 128, SMEM_DYN>>>(adjb, part, psums);
    k_comb    <<<(NH * NN * FO / 4) / 256, 256>>>(out);
}

// round 9
// speedup vs baseline: 1.3288x; 1.0917x over previous
#include <cuda_runtime.h>
#include <cuda_fp16.h>
#include <cstdint>

#define NN    4096
#define FIN   128
#define NH    8
#define FO    64
#define FTOT  512
#define KT    64
#define NSPL  2
#define JSPL  (NN / NSPL)          // 2048 j per split
#define NKT   (JSPL / KT)          // 32 tiles per split
#define LOG2E 1.4426950408889634f

#define VROWS   72                 // 64 data n-rows + 8 (ones/zeros) rows
#define VSTR    72                 // f16 per SMEM row (64 k + 8 pad)
#define STG_V   (VROWS * VSTR * 2) // 10368 B per stage
#define STG_T   512                // 32 float4 per stage
#define SMEM_DYN (3 * STG_V + 3 * STG_T)

// ---------------- scratch (static device memory only) ----------------
__device__ float g_src[NH * NN];
__device__ unsigned g_Tbits[NH];               // static zero-init; atomicMax is
                                               // idempotent across graph replays
__device__ unsigned g_adjb[NN * NN / 32];      // 2 MB bit-packed adjacency
__device__ __half g_vh[NH * FO * NN];          // 4 MB V^T f16: [h][o][j]
__device__ float4 g_tp[NH * (NN / 2)];         // 256 KB pair table {L0,L1,T0,T1}
__device__ float g_part[NSPL][NH * NN * FO];   // 16 MB split numerators
__device__ float g_psum[NSPL][NH * NN];        // split denominators

// ---------------- helpers ----------------
__device__ __forceinline__ unsigned encf(float f) {
    unsigned b = __float_as_uint(f);
    return (b & 0x80000000u) ? ~b : (b | 0x80000000u);
}
__device__ __forceinline__ float decf(unsigned k) {
    unsigned b = (k & 0x80000000u) ? (k & 0x7FFFFFFFu) : ~k;
    return __uint_as_float(b);
}
__device__ __forceinline__ float ex2f(float x) {
    float r;
    asm("ex2.approx.f32 %0, %1;" : "=f"(r) : "f"(x));
    return r;
}
__device__ __forceinline__ unsigned long long pack2(float x, float y) {
    unsigned long long r;
    asm("mov.b64 %0, {%1, %2};" : "=l"(r) : "f"(x), "f"(y));
    return r;
}
__device__ __forceinline__ void unpack2(unsigned long long v, float& x, float& y) {
    asm("mov.b64 {%0, %1}, %2;" : "=f"(x), "=f"(y) : "l"(v));
}
__device__ __forceinline__ unsigned long long add2(unsigned long long a,
                                                   unsigned long long b) {
    unsigned long long d;
    asm("add.rn.f32x2 %0, %1, %2;" : "=l"(d) : "l"(a), "l"(b));
    return d;
}
__device__ __forceinline__ unsigned long long ffma2(unsigned long long a,
                                                    unsigned long long b,
                                                    unsigned long long c) {
    unsigned long long d;
    asm("fma.rn.f32x2 %0, %1, %2, %3;" : "=l"(d) : "l"(a), "l"(b), "l"(c));
    return d;
}
__device__ __forceinline__ uint32_t f16x2(float lo, float hi) {
    uint32_t r;
    asm("cvt.rn.f16x2.f32 %0, %1, %2;" : "=r"(r) : "f"(hi), "f"(lo));
    return r;
}
__device__ __forceinline__ uint32_t smem_u32(const void* p) {
    uint32_t a;
    asm("{ .reg .u64 t; cvta.to.shared.u64 t, %1; cvt.u32.u64 %0, t; }"
        : "=r"(a) : "l"(p));
    return a;
}
__device__ __forceinline__ void cp16(uint32_t dst, const void* src) {
    asm volatile("cp.async.cg.shared.global [%0], [%1], 16;"
                 :: "r"(dst), "l"(src) : "memory");
}
__device__ __forceinline__ void cp_commit() {
    asm volatile("cp.async.commit_group;" ::: "memory");
}
__device__ __forceinline__ void mma_f16(float c[4], uint32_t a0, uint32_t a1,
                                        uint32_t a2, uint32_t a3,
                                        uint32_t b0, uint32_t b1) {
    asm volatile(
        "mma.sync.aligned.m16n8k16.row.col.f32.f16.f16.f32 "
        "{%0,%1,%2,%3}, {%4,%5,%6,%7}, {%8,%9}, {%0,%1,%2,%3};"
        : "+f"(c[0]), "+f"(c[1]), "+f"(c[2]), "+f"(c[3])
        : "r"(a0), "r"(a1), "r"(a2), "r"(a3), "r"(b0), "r"(b1));
}

// ---------------- kernel A: hW GEMM + fused preprocessing (correct reshape) ----------------
// hW is (4096 x 512) row-major; tf-reshape identity:
//   ht[h][n][o] = hW_flat[h*262144 + n*64 + o]
//   => hW[n'][c'] belongs to head h = n'/512, node n = (n'%512)*8 + c'/64, o = c'%64.
// Block (rb, cb): hW rows rb*64..+63, cols cb*64..+63  => head h = rb/8,
// nodes n = ((rb%8)*64 + r)*8 + cb (r = 0..63), features o = 0..63.
__global__ void __launch_bounds__(256)
k_gemmpack(const float* __restrict__ H, const float* __restrict__ W,
           const float* __restrict__ aprm, const int* __restrict__ adj) {
    __shared__ float sA[64][68];
    __shared__ float sW[64][64];
    const int rb = blockIdx.x, cb = blockIdx.y, t = threadIdx.x;
    const int row0 = rb * 64, col0 = cb * 64;
    const int h = rb >> 3, rb8 = rb & 7;
    const int r = t >> 3, c0 = (t & 7) * 8;

    unsigned long long accP[2][4];
#pragma unroll
    for (int i = 0; i < 2; ++i)
#pragma unroll
        for (int p = 0; p < 4; ++p) accP[i][p] = 0ull;

    for (int kk = 0; kk < FIN; kk += 64) {
#pragma unroll
        for (int u = 0; u < 4; ++u) {
            int idx = t + u * 256;
            int rr = idx >> 4, q = idx & 15;
            float4 v = *(const float4*)(H + (size_t)(row0 + rr) * FIN + kk + q * 4);
            *(float4*)&sA[rr][q * 4] = v;
        }
#pragma unroll
        for (int u = 0; u < 4; ++u) {
            int idx = t + u * 256;
            int k = idx >> 4, q = idx & 15;
            float4 v = *(const float4*)(W + (size_t)(kk + k) * FTOT + col0 + q * 4);
            *(float4*)&sW[k][q * 4] = v;
        }
        __syncthreads();
#pragma unroll
        for (int k = 0; k < 64; ++k) {
            unsigned long long a0P = pack2(sA[r][k], sA[r][k]);
            unsigned long long a1P = pack2(sA[r + 32][k], sA[r + 32][k]);
            const unsigned long long* wP = (const unsigned long long*)&sW[k][c0];
#pragma unroll
            for (int p = 0; p < 4; ++p) {
                accP[0][p] = ffma2(a0P, wP[p], accP[0][p]);
                accP[1][p] = ffma2(a1P, wP[p], accP[1][p]);
            }
        }
        __syncthreads();
    }

    // ---- unpack accumulators: v0 = row r cols c0..c0+7, v1 = row r+32 ----
    float v0[8], v1[8];
#pragma unroll
    for (int p = 0; p < 4; ++p) {
        unpack2(accP[0][p], v0[2 * p], v0[2 * p + 1]);
        unpack2(accP[1][p], v1[2 * p], v1[2 * p + 1]);
    }

    // ---- src/tgt dots over o (= block-local cols); scatter at remapped n ----
    {
        const float* ap = aprm + h * 128 + c0;       // o = c0..c0+7
        float s0 = 0.f, s1 = 0.f, tg0 = 0.f, tg1 = 0.f;
#pragma unroll
        for (int k = 0; k < 8; ++k) {
            float av = ap[k], bv = ap[64 + k];
            s0 = fmaf(v0[k], av, s0); tg0 = fmaf(v0[k], bv, tg0);
            s1 = fmaf(v1[k], av, s1); tg1 = fmaf(v1[k], bv, tg1);
        }
#pragma unroll
        for (int off = 4; off; off >>= 1) {
            s0  += __shfl_down_sync(0xFFFFFFFFu, s0, off, 8);
            s1  += __shfl_down_sync(0xFFFFFFFFu, s1, off, 8);
            tg0 += __shfl_down_sync(0xFFFFFFFFu, tg0, off, 8);
            tg1 += __shfl_down_sync(0xFFFFFFFFu, tg1, off, 8);
        }
        if ((t & 7) == 0) {
            const int n0 = (rb8 * 64 + r) * 8 + cb;
            const int n1 = (rb8 * 64 + r + 32) * 8 + cb;
            g_src[h * NN + n0] = s0;
            g_src[h * NN + n1] = s1;
            unsigned e0 = encf(tg0), e1 = encf(tg1);
            atomicMax(&g_Tbits[h], e0 > e1 ? e0 : e1);
            // pair table: component (cb&1) of float4 at pair index n/2
            float* f0 = (float*)&g_tp[h * (NN / 2) + (n0 >> 1)];
            f0[cb & 1]       = tg0 * LOG2E;
            f0[2 + (cb & 1)] = tg0 * (0.2f * LOG2E);
            float* f1 = (float*)&g_tp[h * (NN / 2) + (n1 >> 1)];
            f1[cb & 1]       = tg1 * LOG2E;
            f1[2 + (cb & 1)] = tg1 * (0.2f * LOG2E);
        }
    }

    // ---- stage output tile in SMEM for the V^T scatter ----
#pragma unroll
    for (int k = 0; k < 8; ++k) {
        sA[r][c0 + k]      = v0[k];
        sA[r + 32][c0 + k] = v1[k];
    }
    __syncthreads();

    // ---- V^T f16 scatter: g_vh[h][o][n],  n = (rb8*64 + r)*8 + cb ----
    {
        const int o = t >> 2, rq = (t & 3) * 16;
        __half* vout = g_vh + ((size_t)h * FO + o) * NN + (size_t)rb8 * 512 + cb;
#pragma unroll
        for (int jj = 0; jj < 16; ++jj) {
            int r2 = rq + jj;
            vout[r2 * 8] = __float2half(sA[r2][o]);
        }
    }

    // ---- adjacency bit-pack (independent, DRAM-bound, overlaps GEMM waves) ----
    const int lane = t & 31;
    const int bflat = cb * gridDim.x + rb;           // 0..511
    const int gw0 = bflat * 8 + (t >> 5);
    const int NW = NN * NN / 32;
    for (int w = gw0; w < NW; w += 4096) {
        int v = adj[(size_t)w * 32 + lane];
        unsigned m = __ballot_sync(0xFFFFFFFFu, v != 0);
        if (lane == 0) g_adjb[w] = m;
    }
}

// ---------------- kernel C: fused masked-softmax @ V (fp16 m16n8k16) ----------------
__global__ void __launch_bounds__(128, 4)
k_attn_mma(const unsigned* __restrict__ adjb, float* __restrict__ part,
           float* __restrict__ psums) {
    extern __shared__ float dynf[];
    __half* svh = (__half*)dynf;

    const int head  = blockIdx.x;
    const int ibase = blockIdx.y * 128;
    const int spl   = blockIdx.z;
    const int jbase = spl * JSPL;
    const int t     = threadIdx.x;
    const int wid   = t >> 5;
    const int lane  = t & 31;
    const int g     = lane >> 2;
    const int tg4   = lane & 3;

    const int rbase = ibase + wid * 32 + g;       // rows rbase + {0,8,16,24}

    const float Th = decf(g_Tbits[head]);
    unsigned long long srcP[4], src02P[4];
#pragma unroll
    for (int rg = 0; rg < 4; ++rg) {
        float src = g_src[head * NN + rbase + rg * 8];
        float e0 = src + Th;
        float mm = fmaxf(e0, 0.2f * e0) * LOG2E;  // >= scaled row max
        srcP[rg]   = pack2(src * LOG2E - mm, src * LOG2E - mm);
        src02P[rg] = pack2(src * (0.2f * LOG2E) - mm, src * (0.2f * LOG2E) - mm);
    }

    const unsigned* abase = adjb + (size_t)rbase * (NN / 32) + (jbase / 32);
    const __half* vhp = g_vh + (size_t)head * FO * NN + jbase;   // [o][j]
    const float4* tpp = g_tp + (size_t)head * (NN / 2) + jbase / 2;

    const uint32_t svb = smem_u32(dynf);
    const uint32_t stb = svb + 3 * STG_V;
    const float4* stp = (const float4*)((const char*)dynf + 3 * STG_V);

    // rows 64..71 of every stage: row 64 = 1.0 (denominator), 65..71 = 0
    for (int idx = t; idx < 3 * 8 * VSTR; idx += 128) {
        int st = idx / (8 * VSTR), rem = idx % (8 * VSTR);
        int rr = rem / VSTR, kk = rem % VSTR;
        svh[st * (STG_V / 2) + (64 + rr) * VSTR + kk] =
            (rr == 0) ? __float2half(1.0f) : __float2half(0.0f);
    }

    float acc[2][9][4];
#pragma unroll
    for (int gr = 0; gr < 2; ++gr)
#pragma unroll
        for (int nb = 0; nb < 9; ++nb)
#pragma unroll
            for (int q = 0; q < 4; ++q) acc[gr][nb][q] = 0.f;

    auto load_tile = [&](int kt, int st) {
        const __half* base = vhp + (size_t)kt * KT;
        const uint32_t sb = svb + (uint32_t)st * STG_V;
#pragma unroll
        for (int u = 0; u < 4; ++u) {
            int idx = t + u * 128;            // 512 16B chunks (64 rows x 8)
            int r = idx >> 3, q = idx & 7;
            cp16(sb + (uint32_t)r * (VSTR * 2) + (uint32_t)q * 16,
                 base + (size_t)r * NN + q * 8);
        }
        if (t < 32)
            cp16(stb + (uint32_t)st * STG_T + (uint32_t)t * 16, tpp + kt * 32 + t);
        cp_commit();
    };
    auto load_adj = [&](int kt, unsigned long long wb[4]) {
#pragma unroll
        for (int rg = 0; rg < 4; ++rg) {
            uint2 w2 = *(const uint2*)(abase + (size_t)rg * 8 * (NN / 32) + 2 * kt);
            wb[rg] = (unsigned long long)w2.x | ((unsigned long long)w2.y << 32);
        }
    };

    load_tile(0, 0);
    load_tile(1, 1);
    unsigned long long wbcur[4], wbnext[4];
    load_adj(0, wbcur);

    for (int kt = 0; kt < NKT; ++kt) {
        const int st = kt % 3;
        if (kt + 2 < NKT) {
            asm volatile("cp.async.wait_group 1;" ::: "memory");
        } else {
            asm volatile("cp.async.wait_group 0;" ::: "memory");
        }
        __syncthreads();
        if (kt + 2 < NKT) load_tile(kt + 2, (kt + 2) % 3);
        if (kt + 1 < NKT) load_adj(kt + 1, wbnext);

        const __half* sVs = svh + st * (STG_V / 2);
        const float4* stq = stp + st * 32;

#pragma unroll
        for (int ks = 0; ks < 4; ++ks) {
            const float4 q1 = stq[ks * 8 + tg4];        // cols 2tg4, 2tg4+1
            const float4 q2 = stq[ks * 8 + 4 + tg4];    // cols 2tg4+8, +9
            const unsigned long long tAL = pack2(q1.x, q1.y);
            const unsigned long long tA2 = pack2(q1.z, q1.w);
            const unsigned long long tBL = pack2(q2.x, q2.y);
            const unsigned long long tB2 = pack2(q2.z, q2.w);
            const int shft = ks * 16 + 2 * tg4;

            uint32_t alo[4], ahi[4];
#pragma unroll
            for (int rg = 0; rg < 4; ++rg) {
                const unsigned bs = (unsigned)(wbcur[rg] >> shft);
                float x1, y1, x2, y2;
                unpack2(add2(srcP[rg], tAL), x1, y1);
                unpack2(add2(src02P[rg], tA2), x2, y2);
                float w0 = ex2f(fmaxf(x1, x2)); w0 = (bs & 1u)   ? w0 : 0.f;
                float w1 = ex2f(fmaxf(y1, y2)); w1 = (bs & 2u)   ? w1 : 0.f;
                alo[rg] = f16x2(w0, w1);
                unpack2(add2(srcP[rg], tBL), x1, y1);
                unpack2(add2(src02P[rg], tB2), x2, y2);
                float w2 = ex2f(fmaxf(x1, x2)); w2 = (bs & 256u) ? w2 : 0.f;
                float w3 = ex2f(fmaxf(y1, y2)); w3 = (bs & 512u) ? w3 : 0.f;
                ahi[rg] = f16x2(w2, w3);
            }
            const int kb = ks * 16 + 2 * tg4;
#pragma unroll
            for (int nb = 0; nb < 9; ++nb) {
                const __half* brow = sVs + (nb * 8 + g) * VSTR + kb;
                uint32_t b0 = *(const uint32_t*)(brow);
                uint32_t b1 = *(const uint32_t*)(brow + 8);
                mma_f16(acc[0][nb], alo[0], alo[1], ahi[0], ahi[1], b0, b1);
                mma_f16(acc[1][nb], alo[2], alo[3], ahi[2], ahi[3], b0, b1);
            }
        }
#pragma unroll
        for (int rg = 0; rg < 4; ++rg) wbcur[rg] = wbnext[rg];
    }

    // ---- denominator partials (ones-row n=64 -> tg4==0, c0/c2) ----
    float* psp = psums + (size_t)spl * (NH * NN) + head * NN;
    if (tg4 == 0) {
        psp[rbase]      = acc[0][8][0];
        psp[rbase + 8]  = acc[0][8][2];
        psp[rbase + 16] = acc[1][8][0];
        psp[rbase + 24] = acc[1][8][2];
    }

    // ---- numerator partials ----
    float* pp = part + (size_t)spl * (NH * NN * FO) + ((size_t)head * NN) * FO;
#pragma unroll
    for (int gr = 0; gr < 2; ++gr) {
        float* o1 = pp + (size_t)(rbase + gr * 16) * FO + 2 * tg4;
        float* o2 = o1 + 8 * FO;
#pragma unroll
        for (int nb = 0; nb < 8; ++nb) {
            *(float2*)(o1 + nb * 8) = make_float2(acc[gr][nb][0], acc[gr][nb][1]);
            *(float2*)(o2 + nb * 8) = make_float2(acc[gr][nb][2], acc[gr][nb][3]);
        }
    }
}

// ---------------- combine splits ----------------
__global__ void k_comb(float* __restrict__ out) {
    const int idx = blockIdx.x * blockDim.x + threadIdx.x;   // f4 index
    const int row = idx >> 4;                                // (h*NN + i)
    float4 n0 = *(const float4*)(&g_part[0][(size_t)idx * 4]);
    float4 n1 = *(const float4*)(&g_part[1][(size_t)idx * 4]);
    float s = g_psum[0][row] + g_psum[1][row];
    float inv = (s > 0.f) ? 1.0f / s : 0.f;
    float4 o;
    o.x = (n0.x + n1.x) * inv;
    o.y = (n0.y + n1.y) * inv;
    o.z = (n0.z + n1.z) * inv;
    o.w = (n0.w + n1.w) * inv;
    *(float4*)(out + (size_t)idx * 4) = o;
}

// ---------------- host launcher ----------------
extern "C" void kernel_launch(void* const* d_in, const int* in_sizes, int n_in,
                              void* d_out, int out_size) {
    const float* H = nullptr; const int* adj = nullptr;
    const float* W = nullptr; const float* a = nullptr;
    for (int i = 0; i < n_in; ++i) {
        switch (in_sizes[i]) {
            case NN * FIN:    H   = (const float*)d_in[i]; break;
            case NN * NN:     adj = (const int*)d_in[i];   break;
            case FIN * FTOT:  W   = (const float*)d_in[i]; break;
            case NH * 2 * FO: a   = (const float*)d_in[i]; break;
        }
    }
    float* out = (float*)d_out;

    unsigned* adjb; cudaGetSymbolAddress((void**)&adjb, g_adjb);
    float* part;    cudaGetSymbolAddress((void**)&part, g_part);
    float* psums;   cudaGetSymbolAddress((void**)&psums, g_psum);

    cudaFuncSetAttribute(k_attn_mma, cudaFuncAttributeMaxDynamicSharedMemorySize,
                         SMEM_DYN);

    k_gemmpack<<<dim3(NN / 64, NH), 256>>>(H, W, a, adj);
    k_attn_mma<<<dim3(NH, NN / 128, NSPL), 128, SMEM_DYN>>>(adjb, part, psums);
    k_comb    <<<(NH * NN * FO / 4) / 256, 256>>>(out);
}

// round 10
// speedup vs baseline: 1.4823x; 1.1154x over previous
#include <cuda_runtime.h>
#include <cuda_fp16.h>
#include <cstdint>

#define NN    4096
#define FIN   128
#define NH    8
#define FO    64
#define FTOT  512
#define KT    64
#define NSPL  2
#define JSPL  (NN / NSPL)          // 2048 j per split
#define NKT   (JSPL / KT)          // 32 tiles per split
#define LOG2E 1.4426950408889634f

#define VROWS   72                 // 64 data n-rows + 8 (ones/zeros) rows
#define VSTR    72                 // f16 per SMEM row (64 k + 8 pad)
#define STG_V   (VROWS * VSTR * 2) // 10368 B per stage
#define STG_T   512                // 32 float4 per stage
#define SMEM_DYN (3 * STG_V + 3 * STG_T)

// ---------------- scratch (static device memory only) ----------------
__device__ float g_src[NH * NN];
__device__ unsigned g_Tbits[NH];               // static zero-init; atomicMax is
                                               // idempotent across graph replays
__device__ unsigned g_adjb[NN * NN / 32];      // 2 MB bit-packed adjacency
__device__ __half g_vh[NH * FO * NN];          // 4 MB V^T f16: [h][o][j]
__device__ float4 g_tp[NH * (NN / 2)];         // 256 KB pair table {L0,L1,T0,T1}
__device__ float g_part[NSPL][NH * NN * FO];   // 16 MB split numerators
__device__ float g_psum[NSPL][NH * NN];        // split denominators

// ---------------- helpers ----------------
__device__ __forceinline__ unsigned encf(float f) {
    unsigned b = __float_as_uint(f);
    return (b & 0x80000000u) ? ~b : (b | 0x80000000u);
}
__device__ __forceinline__ float decf(unsigned k) {
    unsigned b = (k & 0x80000000u) ? (k & 0x7FFFFFFFu) : ~k;
    return __uint_as_float(b);
}
__device__ __forceinline__ float ex2f(float x) {
    float r;
    asm("ex2.approx.f32 %0, %1;" : "=f"(r) : "f"(x));
    return r;
}
__device__ __forceinline__ unsigned long long pack2(float x, float y) {
    unsigned long long r;
    asm("mov.b64 %0, {%1, %2};" : "=l"(r) : "f"(x), "f"(y));
    return r;
}
__device__ __forceinline__ void unpack2(unsigned long long v, float& x, float& y) {
    asm("mov.b64 {%0, %1}, %2;" : "=f"(x), "=f"(y) : "l"(v));
}
__device__ __forceinline__ unsigned long long add2(unsigned long long a,
                                                   unsigned long long b) {
    unsigned long long d;
    asm("add.rn.f32x2 %0, %1, %2;" : "=l"(d) : "l"(a), "l"(b));
    return d;
}
__device__ __forceinline__ unsigned long long ffma2(unsigned long long a,
                                                    unsigned long long b,
                                                    unsigned long long c) {
    unsigned long long d;
    asm("fma.rn.f32x2 %0, %1, %2, %3;" : "=l"(d) : "l"(a), "l"(b), "l"(c));
    return d;
}
__device__ __forceinline__ uint32_t f16x2(float lo, float hi) {
    uint32_t r;
    asm("cvt.rn.f16x2.f32 %0, %1, %2;" : "=r"(r) : "f"(hi), "f"(lo));
    return r;
}
__device__ __forceinline__ uint32_t smem_u32(const void* p) {
    uint32_t a;
    asm("{ .reg .u64 t; cvta.to.shared.u64 t, %1; cvt.u32.u64 %0, t; }"
        : "=r"(a) : "l"(p));
    return a;
}
__device__ __forceinline__ void cp16(uint32_t dst, const void* src) {
    asm volatile("cp.async.cg.shared.global [%0], [%1], 16;"
                 :: "r"(dst), "l"(src) : "memory");
}
__device__ __forceinline__ void cp_commit() {
    asm volatile("cp.async.commit_group;" ::: "memory");
}
__device__ __forceinline__ void mma_f16(float c[4], uint32_t a0, uint32_t a1,
                                        uint32_t a2, uint32_t a3,
                                        uint32_t b0, uint32_t b1) {
    asm volatile(
        "mma.sync.aligned.m16n8k16.row.col.f32.f16.f16.f32 "
        "{%0,%1,%2,%3}, {%4,%5,%6,%7}, {%8,%9}, {%0,%1,%2,%3};"
        : "+f"(c[0]), "+f"(c[1]), "+f"(c[2]), "+f"(c[3])
        : "r"(a0), "r"(a1), "r"(a2), "r"(a3), "r"(b0), "r"(b1));
}

// ---------------- kernel A: hW GEMM + fused preprocessing ----------------
// hW (4096 x 512) row-major; ht[h][n][o] = hW_flat[h*262144 + n*64 + o]
// Block (rb, cb): head h = rb/8, nodes n = ((rb%8)*64 + r)*8 + cb, o = 0..63.
__global__ void __launch_bounds__(256)
k_gemmpack(const float* __restrict__ H, const float* __restrict__ W,
           const float* __restrict__ aprm, const int* __restrict__ adj) {
    __shared__ float sA[64][68];
    __shared__ float sW[64][64];
    const int rb = blockIdx.x, cb = blockIdx.y, t = threadIdx.x;
    const int row0 = rb * 64, col0 = cb * 64;
    const int h = rb >> 3, rb8 = rb & 7;
    const int r = t >> 3, c0 = (t & 7) * 8;

    unsigned long long accP[2][4];
#pragma unroll
    for (int i = 0; i < 2; ++i)
#pragma unroll
        for (int p = 0; p < 4; ++p) accP[i][p] = 0ull;

    for (int kk = 0; kk < FIN; kk += 64) {
#pragma unroll
        for (int u = 0; u < 4; ++u) {
            int idx = t + u * 256;
            int rr = idx >> 4, q = idx & 15;
            float4 v = *(const float4*)(H + (size_t)(row0 + rr) * FIN + kk + q * 4);
            *(float4*)&sA[rr][q * 4] = v;
        }
#pragma unroll
        for (int u = 0; u < 4; ++u) {
            int idx = t + u * 256;
            int k = idx >> 4, q = idx & 15;
            float4 v = *(const float4*)(W + (size_t)(kk + k) * FTOT + col0 + q * 4);
            *(float4*)&sW[k][q * 4] = v;
        }
        __syncthreads();
#pragma unroll
        for (int k = 0; k < 64; ++k) {
            unsigned long long a0P = pack2(sA[r][k], sA[r][k]);
            unsigned long long a1P = pack2(sA[r + 32][k], sA[r + 32][k]);
            const unsigned long long* wP = (const unsigned long long*)&sW[k][c0];
#pragma unroll
            for (int p = 0; p < 4; ++p) {
                accP[0][p] = ffma2(a0P, wP[p], accP[0][p]);
                accP[1][p] = ffma2(a1P, wP[p], accP[1][p]);
            }
        }
        __syncthreads();
    }

    // ---- unpack accumulators: v0 = row r cols c0..c0+7, v1 = row r+32 ----
    float v0[8], v1[8];
#pragma unroll
    for (int p = 0; p < 4; ++p) {
        unpack2(accP[0][p], v0[2 * p], v0[2 * p + 1]);
        unpack2(accP[1][p], v1[2 * p], v1[2 * p + 1]);
    }

    // ---- src/tgt dots over o; scatter at remapped n ----
    {
        const float* ap = aprm + h * 128 + c0;
        float s0 = 0.f, s1 = 0.f, tg0 = 0.f, tg1 = 0.f;
#pragma unroll
        for (int k = 0; k < 8; ++k) {
            float av = ap[k], bv = ap[64 + k];
            s0 = fmaf(v0[k], av, s0); tg0 = fmaf(v0[k], bv, tg0);
            s1 = fmaf(v1[k], av, s1); tg1 = fmaf(v1[k], bv, tg1);
        }
#pragma unroll
        for (int off = 4; off; off >>= 1) {
            s0  += __shfl_down_sync(0xFFFFFFFFu, s0, off, 8);
            s1  += __shfl_down_sync(0xFFFFFFFFu, s1, off, 8);
            tg0 += __shfl_down_sync(0xFFFFFFFFu, tg0, off, 8);
            tg1 += __shfl_down_sync(0xFFFFFFFFu, tg1, off, 8);
        }
        if ((t & 7) == 0) {
            const int n0 = (rb8 * 64 + r) * 8 + cb;
            const int n1 = (rb8 * 64 + r + 32) * 8 + cb;
            g_src[h * NN + n0] = s0;
            g_src[h * NN + n1] = s1;
            unsigned e0 = encf(tg0), e1 = encf(tg1);
            atomicMax(&g_Tbits[h], e0 > e1 ? e0 : e1);
            float* f0 = (float*)&g_tp[h * (NN / 2) + (n0 >> 1)];
            f0[cb & 1]       = tg0 * LOG2E;
            f0[2 + (cb & 1)] = tg0 * (0.2f * LOG2E);
            float* f1 = (float*)&g_tp[h * (NN / 2) + (n1 >> 1)];
            f1[cb & 1]       = tg1 * LOG2E;
            f1[2 + (cb & 1)] = tg1 * (0.2f * LOG2E);
        }
    }

    // ---- stage output tile in SMEM for the V^T scatter ----
#pragma unroll
    for (int k = 0; k < 8; ++k) {
        sA[r][c0 + k]      = v0[k];
        sA[r + 32][c0 + k] = v1[k];
    }
    __syncthreads();

    // ---- V^T f16 scatter: g_vh[h][o][n],  n = (rb8*64 + r)*8 + cb ----
    {
        const int o = t >> 2, rq = (t & 3) * 16;
        __half* vout = g_vh + ((size_t)h * FO + o) * NN + (size_t)rb8 * 512 + cb;
#pragma unroll
        for (int jj = 0; jj < 16; ++jj) {
            int r2 = rq + jj;
            vout[r2 * 8] = __float2half(sA[r2][o]);
        }
    }

    // ---- adjacency bit-pack: int4 loads + shuffle nibble assembly (MLP>=4) ----
    // warp iteration covers 128 ints (512B); 3 shfl steps build 4 packed words
    // in lanes 0,8,16,24. ~32 iterations/warp, unrolled for latency overlap.
    {
        const int lane = t & 31;
        const int bflat = cb * gridDim.x + rb;           // 0..511
        const int gw0 = bflat * 8 + (t >> 5);            // warp id 0..4095
        const int NC = NN * NN / 128;                    // 131072 int4-chunks
        const int4* adj4 = (const int4*)adj;
#pragma unroll 4
        for (int w = gw0; w < NC; w += 4096) {
            int4 v = adj4[(size_t)w * 32 + lane];
            unsigned nib = (unsigned)(v.x != 0) | ((unsigned)(v.y != 0) << 1) |
                           ((unsigned)(v.z != 0) << 2) | ((unsigned)(v.w != 0) << 3);
            nib |= __shfl_down_sync(0xFFFFFFFFu, nib, 1) << 4;
            nib |= __shfl_down_sync(0xFFFFFFFFu, nib, 2) << 8;
            nib |= __shfl_down_sync(0xFFFFFFFFu, nib, 4) << 16;
            if ((lane & 7) == 0) g_adjb[w * 4 + (lane >> 3)] = nib;
        }
    }
}

// ---------------- kernel C: fused masked-softmax @ V (fp16 m16n8k16) ----------------
__global__ void __launch_bounds__(128, 4)
k_attn_mma(const unsigned* __restrict__ adjb, float* __restrict__ part,
           float* __restrict__ psums) {
    extern __shared__ float dynf[];
    __half* svh = (__half*)dynf;

    const int head  = blockIdx.x;
    const int ibase = blockIdx.y * 128;
    const int spl   = blockIdx.z;
    const int jbase = spl * JSPL;
    const int t     = threadIdx.x;
    const int wid   = t >> 5;
    const int lane  = t & 31;
    const int g     = lane >> 2;
    const int tg4   = lane & 3;

    const int rbase = ibase + wid * 32 + g;       // rows rbase + {0,8,16,24}

    const float Th = decf(g_Tbits[head]);
    unsigned long long srcP[4], src02P[4];
#pragma unroll
    for (int rg = 0; rg < 4; ++rg) {
        float src = g_src[head * NN + rbase + rg * 8];
        float e0 = src + Th;
        float mm = fmaxf(e0, 0.2f * e0) * LOG2E;  // >= scaled row max
        srcP[rg]   = pack2(src * LOG2E - mm, src * LOG2E - mm);
        src02P[rg] = pack2(src * (0.2f * LOG2E) - mm, src * (0.2f * LOG2E) - mm);
    }

    const unsigned* abase = adjb + (size_t)rbase * (NN / 32) + (jbase / 32);
    const __half* vhp = g_vh + (size_t)head * FO * NN + jbase;   // [o][j]
    const float4* tpp = g_tp + (size_t)head * (NN / 2) + jbase / 2;

    const uint32_t svb = smem_u32(dynf);
    const uint32_t stb = svb + 3 * STG_V;
    const float4* stp = (const float4*)((const char*)dynf + 3 * STG_V);

    // rows 64..71 of every stage: row 64 = 1.0 (denominator), 65..71 = 0
    for (int idx = t; idx < 3 * 8 * VSTR; idx += 128) {
        int st = idx / (8 * VSTR), rem = idx % (8 * VSTR);
        int rr = rem / VSTR, kk = rem % VSTR;
        svh[st * (STG_V / 2) + (64 + rr) * VSTR + kk] =
            (rr == 0) ? __float2half(1.0f) : __float2half(0.0f);
    }

    float acc[2][9][4];
#pragma unroll
    for (int gr = 0; gr < 2; ++gr)
#pragma unroll
        for (int nb = 0; nb < 9; ++nb)
#pragma unroll
            for (int q = 0; q < 4; ++q) acc[gr][nb][q] = 0.f;

    auto load_tile = [&](int kt, int st) {
        const __half* base = vhp + (size_t)kt * KT;
        const uint32_t sb = svb + (uint32_t)st * STG_V;
#pragma unroll
        for (int u = 0; u < 4; ++u) {
            int idx = t + u * 128;            // 512 16B chunks (64 rows x 8)
            int r = idx >> 3, q = idx & 7;
            cp16(sb + (uint32_t)r * (VSTR * 2) + (uint32_t)q * 16,
                 base + (size_t)r * NN + q * 8);
        }
        if (t < 32)
            cp16(stb + (uint32_t)st * STG_T + (uint32_t)t * 16, tpp + kt * 32 + t);
        cp_commit();
    };
    auto load_adj = [&](int kt, unsigned long long wb[4]) {
#pragma unroll
        for (int rg = 0; rg < 4; ++rg) {
            uint2 w2 = *(const uint2*)(abase + (size_t)rg * 8 * (NN / 32) + 2 * kt);
            wb[rg] = (unsigned long long)w2.x | ((unsigned long long)w2.y << 32);
        }
    };

    load_tile(0, 0);
    load_tile(1, 1);
    unsigned long long wbcur[4], wbnext[4];
    load_adj(0, wbcur);

    for (int kt = 0; kt < NKT; ++kt) {
        const int st = kt % 3;
        if (kt + 2 < NKT) {
            asm volatile("cp.async.wait_group 1;" ::: "memory");
        } else {
            asm volatile("cp.async.wait_group 0;" ::: "memory");
        }
        __syncthreads();
        if (kt + 2 < NKT) load_tile(kt + 2, (kt + 2) % 3);
        if (kt + 1 < NKT) load_adj(kt + 1, wbnext);

        const __half* sVs = svh + st * (STG_V / 2);
        const float4* stq = stp + st * 32;

#pragma unroll
        for (int ks = 0; ks < 4; ++ks) {
            const float4 q1 = stq[ks * 8 + tg4];        // cols 2tg4, 2tg4+1
            const float4 q2 = stq[ks * 8 + 4 + tg4];    // cols 2tg4+8, +9
            const unsigned long long tAL = pack2(q1.x, q1.y);
            const unsigned long long tA2 = pack2(q1.z, q1.w);
            const unsigned long long tBL = pack2(q2.x, q2.y);
            const unsigned long long tB2 = pack2(q2.z, q2.w);
            const int shft = ks * 16 + 2 * tg4;

            uint32_t alo[4], ahi[4];
#pragma unroll
            for (int rg = 0; rg < 4; ++rg) {
                const unsigned bs = (unsigned)(wbcur[rg] >> shft);
                float x1, y1, x2, y2;
                unpack2(add2(srcP[rg], tAL), x1, y1);
                unpack2(add2(src02P[rg], tA2), x2, y2);
                float w0 = ex2f(fmaxf(x1, x2)); w0 = (bs & 1u)   ? w0 : 0.f;
                float w1 = ex2f(fmaxf(y1, y2)); w1 = (bs & 2u)   ? w1 : 0.f;
                alo[rg] = f16x2(w0, w1);
                unpack2(add2(srcP[rg], tBL), x1, y1);
                unpack2(add2(src02P[rg], tB2), x2, y2);
                float w2 = ex2f(fmaxf(x1, x2)); w2 = (bs & 256u) ? w2 : 0.f;
                float w3 = ex2f(fmaxf(y1, y2)); w3 = (bs & 512u) ? w3 : 0.f;
                ahi[rg] = f16x2(w2, w3);
            }
            const int kb = ks * 16 + 2 * tg4;
#pragma unroll
            for (int nb = 0; nb < 9; ++nb) {
                const __half* brow = sVs + (nb * 8 + g) * VSTR + kb;
                uint32_t b0 = *(const uint32_t*)(brow);
                uint32_t b1 = *(const uint32_t*)(brow + 8);
                mma_f16(acc[0][nb], alo[0], alo[1], ahi[0], ahi[1], b0, b1);
                mma_f16(acc[1][nb], alo[2], alo[3], ahi[2], ahi[3], b0, b1);
            }
        }
#pragma unroll
        for (int rg = 0; rg < 4; ++rg) wbcur[rg] = wbnext[rg];
    }

    // ---- denominator partials (ones-row n=64 -> tg4==0, c0/c2) ----
    float* psp = psums + (size_t)spl * (NH * NN) + head * NN;
    if (tg4 == 0) {
        psp[rbase]      = acc[0][8][0];
        psp[rbase + 8]  = acc[0][8][2];
        psp[rbase + 16] = acc[1][8][0];
        psp[rbase + 24] = acc[1][8][2];
    }

    // ---- numerator partials ----
    float* pp = part + (size_t)spl * (NH * NN * FO) + ((size_t)head * NN) * FO;
#pragma unroll
    for (int gr = 0; gr < 2; ++gr) {
        float* o1 = pp + (size_t)(rbase + gr * 16) * FO + 2 * tg4;
        float* o2 = o1 + 8 * FO;
#pragma unroll
        for (int nb = 0; nb < 8; ++nb) {
            *(float2*)(o1 + nb * 8) = make_float2(acc[gr][nb][0], acc[gr][nb][1]);
            *(float2*)(o2 + nb * 8) = make_float2(acc[gr][nb][2], acc[gr][nb][3]);
        }
    }
}

// ---------------- combine splits ----------------
__global__ void k_comb(float* __restrict__ out) {
    const int idx = blockIdx.x * blockDim.x + threadIdx.x;   // f4 index
    const int row = idx >> 4;                                // (h*NN + i)
    float4 n0 = *(const float4*)(&g_part[0][(size_t)idx * 4]);
    float4 n1 = *(const float4*)(&g_part[1][(size_t)idx * 4]);
    float s = g_psum[0][row] + g_psum[1][row];
    float inv = (s > 0.f) ? 1.0f / s : 0.f;
    float4 o;
    o.x = (n0.x + n1.x) * inv;
    o.y = (n0.y + n1.y) * inv;
    o.z = (n0.z + n1.z) * inv;
    o.w = (n0.w + n1.w) * inv;
    *(float4*)(out + (size_t)idx * 4) = o;
}

// ---------------- host launcher ----------------
extern "C" void kernel_launch(void* const* d_in, const int* in_sizes, int n_in,
                              void* d_out, int out_size) {
    const float* H = nullptr; const int* adj = nullptr;
    const float* W = nullptr; const float* a = nullptr;
    for (int i = 0; i < n_in; ++i) {
        switch (in_sizes[i]) {
            case NN * FIN:    H   = (const float*)d_in[i]; break;
            case NN * NN:     adj = (const int*)d_in[i];   break;
            case FIN * FTOT:  W   = (const float*)d_in[i]; break;
            case NH * 2 * FO: a   = (const float*)d_in[i]; break;
        }
    }
    float* out = (float*)d_out;

    unsigned* adjb; cudaGetSymbolAddress((void**)&adjb, g_adjb);
    float* part;    cudaGetSymbolAddress((void**)&part, g_part);
    float* psums;   cudaGetSymbolAddress((void**)&psums, g_psum);

    cudaFuncSetAttribute(k_attn_mma, cudaFuncAttributeMaxDynamicSharedMemorySize,
                         SMEM_DYN);

    k_gemmpack<<<dim3(NN / 64, NH), 256>>>(H, W, a, adj);
    k_attn_mma<<<dim3(NH, NN / 128, NSPL), 128, SMEM_DYN>>>(adjb, part, psums);
    k_comb    <<<(NH * NN * FO / 4) / 256, 256>>>(out);
}